// round 15
// baseline (speedup 1.0000x reference)
#include <cuda_runtime.h>
#include <cuda_bf16.h>
#include <math.h>
#include <stdint.h>

#define B_ 8
#define L_ 2048
#define D_ 1024

static const size_t ND = (size_t)B_ * L_ * D_;   // 16,777,216
static const size_t NW = (size_t)D_ * D_;        // 1,048,576

// ---------------- device scratch (globals: no allocation APIs) ----------------
#define GBUF(name, n) __device__ __align__(256) __nv_bfloat16 name[n]
GBUF(g_xh, 16777216);  GBUF(g_xl, 16777216);
GBUF(g_qih, 16777216); GBUF(g_qil, 16777216);
GBUF(g_vih, 16777216); GBUF(g_vil, 16777216);
GBUF(g_wkh, 1048576);  GBUF(g_wkl, 1048576);
GBUF(g_wqsh, 1048576); GBUF(g_wqsl, 1048576);
GBUF(g_wqoh, 1048576); GBUF(g_wqol, 1048576);
GBUF(g_wvh, 1048576);  GBUF(g_wvl, 1048576);
GBUF(g_kh, 16777216);  GBUF(g_kl, 16777216);
GBUF(g_qsh, 16777216); GBUF(g_qsl, 16777216);
GBUF(g_qoh, 16777216); GBUF(g_qol, 16777216);
GBUF(g_vth, 16777216); GBUF(g_vtl, 16777216);   // V^T hi/lo, written by proj epilogue
GBUF(g_ph, 33554432);  GBUF(g_pl, 33554432);
__device__ __align__(256) float g_po[33554432];

// ---------------- PTX helpers (base sm_103 target: NO tcgen05/TMA) ------------
__device__ __forceinline__ uint32_t smem_u32(const void* p) {
    uint32_t a;
    asm("{ .reg .u64 t; cvta.to.shared.u64 t, %1; cvt.u32.u64 %0, t; }" : "=r"(a) : "l"(p));
    return a;
}

#define CPASYNC(saddr, gptr) \
    asm volatile("cp.async.cg.shared.global [%0], [%1], 16;" \
                 :: "r"(saddr), "l"(gptr) : "memory")
#define CP_COMMIT() asm volatile("cp.async.commit_group;" ::: "memory")
#define CP_WAIT2()  asm volatile("cp.async.wait_group 2;" ::: "memory")

__device__ __forceinline__ void ldmx4(uint32_t* r, uint32_t addr) {
    asm volatile("ldmatrix.sync.aligned.m8n8.x4.shared.b16 {%0,%1,%2,%3}, [%4];"
                 : "=r"(r[0]), "=r"(r[1]), "=r"(r[2]), "=r"(r[3]) : "r"(addr));
}

__device__ __forceinline__ void mma16816(float* c, const uint32_t* a, const uint32_t* b) {
    asm volatile(
        "mma.sync.aligned.m16n8k16.row.col.f32.bf16.bf16.f32 "
        "{%0,%1,%2,%3}, {%4,%5,%6,%7}, {%8,%9}, {%0,%1,%2,%3};"
        : "+f"(c[0]), "+f"(c[1]), "+f"(c[2]), "+f"(c[3])
        : "r"(a[0]), "r"(a[1]), "r"(a[2]), "r"(a[3]), "r"(b[0]), "r"(b[1]));
}

// smem tile rows of 32 bf16 (64B, 4x16B chunks), XOR swizzle on chunk.
__device__ __forceinline__ uint32_t swz(int row, int chunk) {
    return (uint32_t)(row * 64 + (((chunk ^ ((row >> 1) & 3)) & 3) << 4));
}

__device__ __forceinline__ void split2(float v, __nv_bfloat16& h, __nv_bfloat16& l) {
    h = __float2bfloat16(v);
    l = __float2bfloat16(v - __bfloat162float(h));
}

// ---------------- pipelined bf16x3 warp-MMA GEMM body (NT) --------------------
// C[m,n] = sum_k (Ah+Al)[m,k]*(Bh+Bl)[n,k]   (Al*Bl dropped)
// CTA 256x128xK, Kstep=32, 4 stages, 8 warps (4m x 2n), warp tile 64x64.
// Stage layout: Ah[256x32]@0 (16KB), Al@16K, Bh[128x32]@32K (8KB), Bl@40K.
// EPI=0: fp32 C.  EPI=1: bf16 hi/lo split (Ch, Cl).
// EPI=2: bf16 hi/lo split stored TRANSPOSED (Ch/Cl are [B, N-dim, M-dim],
//        row stride ldc, batch = m0>>11 of the flattened M) via smem staging.
#define STG_BYTES 49152
#define GEMM_SMEM (4 * STG_BYTES)   // 192 KB

template <int EPI>
__device__ __forceinline__ void
gemm_body(const __nv_bfloat16* __restrict__ Ah, const __nv_bfloat16* __restrict__ Al,
          const __nv_bfloat16* __restrict__ Bh, const __nv_bfloat16* __restrict__ Bl,
          float* __restrict__ C, __nv_bfloat16* __restrict__ Ch, __nv_bfloat16* __restrict__ Cl,
          int K, int ldc, int m0, int n0)
{
    extern __shared__ __align__(128) char smem[];
    const uint32_t smemU = smem_u32(smem);

    const int tid  = threadIdx.x;
    const int wid  = tid >> 5;
    const int lane = tid & 31;

    const int wm64 = (wid & 3) * 64;
    const int wn64 = (wid >> 2) * 64;

    float acc[128];
    #pragma unroll
    for (int i = 0; i < 128; i++) acc[i] = 0.0f;

    const int KT = K >> 5;   // k-steps of 32

    #define ISSUE_STAGE(KF, SLOT) do {                                        \
        uint32_t _sb = smemU + (uint32_t)(SLOT) * STG_BYTES;                  \
        size_t _ko = (size_t)(KF) * 32;                                       \
        _Pragma("unroll")                                                     \
        for (int _i = 0; _i < 4; _i++) {                                      \
            int _c = tid + _i * 256;                                          \
            int _r = _c >> 2, _ch = _c & 3;                                   \
            uint32_t _so = swz(_r, _ch);                                      \
            size_t _go = (size_t)(m0 + _r) * K + _ko + (size_t)_ch * 8;       \
            CPASYNC(_sb + _so,          Ah + _go);                            \
            CPASYNC(_sb + 16384u + _so, Al + _go);                            \
        }                                                                     \
        _Pragma("unroll")                                                     \
        for (int _i = 0; _i < 2; _i++) {                                      \
            int _c = tid + _i * 256;                                          \
            int _r = _c >> 2, _ch = _c & 3;                                   \
            uint32_t _so = swz(_r, _ch);                                      \
            size_t _go = (size_t)(n0 + _r) * K + _ko + (size_t)_ch * 8;       \
            CPASYNC(_sb + 32768u + _so, Bh + _go);                            \
            CPASYNC(_sb + 40960u + _so, Bl + _go);                            \
        }                                                                     \
    } while (0)

    // prologue: fill 3 stages
    ISSUE_STAGE(0, 0); CP_COMMIT();
    ISSUE_STAGE(1, 1); CP_COMMIT();
    ISSUE_STAGE(2, 2); CP_COMMIT();

    for (int kt = 0; kt < KT; kt++) {
        CP_WAIT2();
        __syncthreads();

        int kf = kt + 3;
        if (kf < KT) ISSUE_STAGE(kf, kf & 3);
        CP_COMMIT();

        const uint32_t sb = smemU + (uint32_t)(kt & 3) * STG_BYTES;
        #pragma unroll
        for (int k16 = 0; k16 < 2; k16++) {
            uint32_t bh[16], bl[16];
            #pragma unroll
            for (int tp = 0; tp < 4; tp++) {
                int brow = wn64 + tp * 16 + (lane & 7) + ((lane >> 4) << 3);
                int bch  = k16 * 2 + ((lane >> 3) & 1);
                uint32_t off = swz(brow, bch);
                ldmx4(&bh[tp * 4], sb + 32768u + off);
                ldmx4(&bl[tp * 4], sb + 40960u + off);
            }
            #pragma unroll
            for (int tm = 0; tm < 4; tm++) {
                int arow = wm64 + tm * 16 + (lane & 15);
                int ach  = k16 * 2 + (lane >> 4);
                uint32_t off = swz(arow, ach);
                uint32_t ah[4], al[4];
                ldmx4(ah, sb + off);
                ldmx4(al, sb + 16384u + off);
                #pragma unroll
                for (int tn = 0; tn < 8; tn++) {
                    float* c = acc + (tm * 8 + tn) * 4;
                    mma16816(c, ah, &bh[tn * 2]);
                    mma16816(c, al, &bh[tn * 2]);
                    mma16816(c, ah, &bl[tn * 2]);
                }
            }
        }
    }
    #undef ISSUE_STAGE

    if (EPI == 2) {
        // ---- transposed split epilogue via smem staging ----
        // stage: hi/lo tiles as [128 n][TS m-padded] bf16
        const int TS = 272;   // padded m-stride (banks spread)
        __nv_bfloat16* sh = reinterpret_cast<__nv_bfloat16*>(smem);
        __nv_bfloat16* sl = sh + 128 * TS;

        __syncthreads();   // mainloop smem no longer needed
        #pragma unroll
        for (int tm = 0; tm < 4; tm++) {
            #pragma unroll
            for (int tn = 0; tn < 8; tn++) {
                const float* c = acc + (tm * 8 + tn) * 4;
                int rl = wm64 + tm * 16 + (lane >> 2);      // local m (0..255)
                int cl = wn64 + tn * 8 + (lane & 3) * 2;    // local n (0..127)
                __nv_bfloat16 h, l;
                split2(c[0], h, l); sh[cl * TS + rl] = h;       sl[cl * TS + rl] = l;
                split2(c[1], h, l); sh[(cl + 1) * TS + rl] = h; sl[(cl + 1) * TS + rl] = l;
                split2(c[2], h, l); sh[cl * TS + rl + 8] = h;   sl[cl * TS + rl + 8] = l;
                split2(c[3], h, l); sh[(cl + 1) * TS + rl + 8] = h; sl[(cl + 1) * TS + rl + 8] = l;
            }
        }
        __syncthreads();

        // write out: C^T tile rows = n0..n0+127 (d), cols = m-range (l), per-batch
        const size_t base = (size_t)(m0 >> 11) * ((size_t)D_ * L_) + (m0 & 2047);
        #pragma unroll
        for (int j = 0; j < 64; j++) {
            int idx = tid + j * 256;          // 16384 uint32 per tile
            int nl  = idx >> 7;
            int ml2 = (idx & 127) * 2;
            uint32_t hp = (uint32_t)__bfloat16_as_ushort(sh[nl * TS + ml2]) |
                          ((uint32_t)__bfloat16_as_ushort(sh[nl * TS + ml2 + 1]) << 16);
            uint32_t lp = (uint32_t)__bfloat16_as_ushort(sl[nl * TS + ml2]) |
                          ((uint32_t)__bfloat16_as_ushort(sl[nl * TS + ml2 + 1]) << 16);
            size_t gx = base + (size_t)(n0 + nl) * L_ + ml2;
            *(uint32_t*)(Ch + gx) = hp;
            *(uint32_t*)(Cl + gx) = lp;
        }
        return;
    }

    // epilogue: direct stores from mma accumulator layout
    #pragma unroll
    for (int tm = 0; tm < 4; tm++) {
        #pragma unroll
        for (int tn = 0; tn < 8; tn++) {
            const float* c = acc + (tm * 8 + tn) * 4;
            int row0 = m0 + wm64 + tm * 16 + (lane >> 2);
            int col  = n0 + wn64 + tn * 8 + (lane & 3) * 2;
            size_t i0 = (size_t)row0 * ldc + col;
            size_t i1 = i0 + (size_t)8 * ldc;
            if (EPI == 0) {
                *(float2*)(C + i0) = make_float2(c[0], c[1]);
                *(float2*)(C + i1) = make_float2(c[2], c[3]);
            } else {
                #pragma unroll
                for (int p = 0; p < 2; p++) {
                    size_t ix = p ? i1 : i0;
                    __nv_bfloat16 h0, l0, h1, l1;
                    split2(c[p * 2], h0, l0);
                    split2(c[p * 2 + 1], h1, l1);
                    uint32_t hp = (uint32_t)__bfloat16_as_ushort(h0) |
                                  ((uint32_t)__bfloat16_as_ushort(h1) << 16);
                    uint32_t lp = (uint32_t)__bfloat16_as_ushort(l0) |
                                  ((uint32_t)__bfloat16_as_ushort(l1) << 16);
                    *(uint32_t*)(Ch + ix) = hp;
                    *(uint32_t*)(Cl + ix) = lp;
                }
            }
        }
    }
}

// ---- merged projection GEMM: z selects one of 4 (A, W, C) tuples --------------
// z==3 is the V projection: writes V^T hi/lo directly (EPI=2).
struct ProjP {
    const __nv_bfloat16 *Ah[4], *Al[4], *Bh[4], *Bl[4];
    __nv_bfloat16 *Ch[4], *Cl[4];
};
__global__ void __launch_bounds__(256, 1)
gemm_proj(ProjP p)
{
    const int g  = blockIdx.z;
    const int m0 = blockIdx.y * 256, n0 = blockIdx.x * 128;
    if (g == 3)
        gemm_body<2>(p.Ah[3], p.Al[3], p.Bh[3], p.Bl[3],
                     nullptr, p.Ch[3], p.Cl[3], 1024, 2048, m0, n0);
    else
        gemm_body<1>(p.Ah[g], p.Al[g], p.Bh[g], p.Bl[g],
                     nullptr, p.Ch[g], p.Cl[g], 1024, 1024, m0, n0);
}

// ---- merged score GEMMs: z = which*8 + batch -----------------------------------
struct ScoreP {
    const __nv_bfloat16 *Qh[2], *Ql[2];
    const __nv_bfloat16 *Kh, *Kl;
    float *C[2];
};
__global__ void __launch_bounds__(256, 1)
gemm_scores(ScoreP p)
{
    const int z = blockIdx.z;
    const int b = z & 7, w = z >> 3;
    const size_t offA = (size_t)b * L_ * D_;
    const int m0 = blockIdx.y * 256, n0 = blockIdx.x * 128;
    gemm_body<0>(p.Qh[w] + offA, p.Ql[w] + offA, p.Kh + offA, p.Kl + offA,
                 p.C[w] + (size_t)b * L_ * L_, nullptr, nullptr, 1024, 2048, m0, n0);
}

// ---- PV GEMM: z = batch ---------------------------------------------------------
__global__ void __launch_bounds__(256, 1)
gemm_pv(const __nv_bfloat16* __restrict__ Ah, const __nv_bfloat16* __restrict__ Al,
        const __nv_bfloat16* __restrict__ Bh, const __nv_bfloat16* __restrict__ Bl,
        float* __restrict__ C)
{
    const size_t z = blockIdx.z;
    const int m0 = blockIdx.y * 256, n0 = blockIdx.x * 128;
    gemm_body<0>(Ah + z * ((size_t)L_ * L_), Al + z * ((size_t)L_ * L_),
                 Bh + z * ((size_t)D_ * L_), Bl + z * ((size_t)D_ * L_),
                 C + z * ((size_t)L_ * D_), nullptr, nullptr, 2048, 1024, m0, n0);
}

// ---------------- fp32 -> bf16 hi/lo split, merged + grid-strided ---------------
struct SplitP { const float4* in[4]; uint2* hi[4]; uint2* lo[4]; };

__global__ void __launch_bounds__(256)
split_many(SplitP p, int n4)
{
    const int g = blockIdx.y;
    const float4* in = p.in[g];
    uint2* hi = p.hi[g];
    uint2* lo = p.lo[g];
    const int stride = gridDim.x * 256;
    for (int i = blockIdx.x * 256 + threadIdx.x; i < n4; i += stride) {
        float4 v = in[i];
        __nv_bfloat16 h0, l0, h1, l1, h2, l2, h3, l3;
        split2(v.x, h0, l0); split2(v.y, h1, l1);
        split2(v.z, h2, l2); split2(v.w, h3, l3);
        uint2 H, L;
        H.x = (uint32_t)__bfloat16_as_ushort(h0) | ((uint32_t)__bfloat16_as_ushort(h1) << 16);
        H.y = (uint32_t)__bfloat16_as_ushort(h2) | ((uint32_t)__bfloat16_as_ushort(h3) << 16);
        L.x = (uint32_t)__bfloat16_as_ushort(l0) | ((uint32_t)__bfloat16_as_ushort(l1) << 16);
        L.y = (uint32_t)__bfloat16_as_ushort(l2) | ((uint32_t)__bfloat16_as_ushort(l3) << 16);
        hi[i] = H; lo[i] = L;
    }
}

// ---------------- dual softmax + combined-p bf16 split (float4 vectorized) ------
__global__ void __launch_bounds__(256)
softmax_combine(const float* __restrict__ mask,
                float* __restrict__ psf,          // raw self scores -> p_self (fp32 out)
                const float* __restrict__ po,     // raw other scores
                __nv_bfloat16* __restrict__ ph,   // (p_self+p_other) hi
                __nv_bfloat16* __restrict__ pl)   // (p_self+p_other) lo
{
    const int row = blockIdx.x;
    const int b   = row >> 11;
    float4* ps4 = (float4*)(psf + (size_t)row * L_);
    const float4* pc4 = (const float4*)(po + (size_t)row * L_);
    uint2* ph2 = (uint2*)(ph + (size_t)row * L_);
    uint2* pl2 = (uint2*)(pl + (size_t)row * L_);
    const float4* mk4 = (const float4*)(mask + (size_t)b * L_);

    const int t = threadIdx.x;
    const float scale = 0.03125f;

    float s[8], o[8];
    #pragma unroll
    for (int j = 0; j < 2; j++) {
        int k = t + j * 256;            // float4 index, 512 per row
        float4 sv = ps4[k];
        float4 ov = pc4[k];
        float4 mv = mk4[k];
        float p0 = (1.0f - mv.x) * -100000.0f;
        float p1 = (1.0f - mv.y) * -100000.0f;
        float p2 = (1.0f - mv.z) * -100000.0f;
        float p3 = (1.0f - mv.w) * -100000.0f;
        s[j*4+0] = sv.x * scale + p0;  o[j*4+0] = ov.x * scale + p0;
        s[j*4+1] = sv.y * scale + p1;  o[j*4+1] = ov.y * scale + p1;
        s[j*4+2] = sv.z * scale + p2;  o[j*4+2] = ov.z * scale + p2;
        s[j*4+3] = sv.w * scale + p3;  o[j*4+3] = ov.w * scale + p3;
    }

    __shared__ float red[2][8];
    const int w = t >> 5, ln = t & 31;

    float ms = -INFINITY, mo = -INFINITY;
    #pragma unroll
    for (int j = 0; j < 8; j++) { ms = fmaxf(ms, s[j]); mo = fmaxf(mo, o[j]); }
    #pragma unroll
    for (int off = 16; off; off >>= 1) {
        ms = fmaxf(ms, __shfl_xor_sync(0xffffffffu, ms, off));
        mo = fmaxf(mo, __shfl_xor_sync(0xffffffffu, mo, off));
    }
    if (ln == 0) { red[0][w] = ms; red[1][w] = mo; }
    __syncthreads();
    ms = red[0][0]; mo = red[1][0];
    #pragma unroll
    for (int i = 1; i < 8; i++) { ms = fmaxf(ms, red[0][i]); mo = fmaxf(mo, red[1][i]); }
    __syncthreads();

    float ss = 0.0f, so = 0.0f;
    #pragma unroll
    for (int j = 0; j < 8; j++) {
        s[j] = expf(s[j] - ms); ss += s[j];
        o[j] = expf(o[j] - mo); so += o[j];
    }
    #pragma unroll
    for (int off = 16; off; off >>= 1) {
        ss += __shfl_xor_sync(0xffffffffu, ss, off);
        so += __shfl_xor_sync(0xffffffffu, so, off);
    }
    if (ln == 0) { red[0][w] = ss; red[1][w] = so; }
    __syncthreads();
    ss = 0.0f; so = 0.0f;
    #pragma unroll
    for (int i = 0; i < 8; i++) { ss += red[0][i]; so += red[1][i]; }

    const float rs = 1.0f / ss, ro = 1.0f / so;
    #pragma unroll
    for (int j = 0; j < 2; j++) {
        int k = t + j * 256;
        float a0 = s[j*4+0] * rs, a1 = s[j*4+1] * rs;
        float a2 = s[j*4+2] * rs, a3 = s[j*4+3] * rs;
        ps4[k] = make_float4(a0, a1, a2, a3);
        float c0 = a0 + o[j*4+0] * ro, c1 = a1 + o[j*4+1] * ro;
        float c2 = a2 + o[j*4+2] * ro, c3 = a3 + o[j*4+3] * ro;
        __nv_bfloat16 h0, l0, h1, l1, h2, l2, h3, l3;
        split2(c0, h0, l0); split2(c1, h1, l1);
        split2(c2, h2, l2); split2(c3, h3, l3);
        uint2 H, L;
        H.x = (uint32_t)__bfloat16_as_ushort(h0) | ((uint32_t)__bfloat16_as_ushort(h1) << 16);
        H.y = (uint32_t)__bfloat16_as_ushort(h2) | ((uint32_t)__bfloat16_as_ushort(h3) << 16);
        L.x = (uint32_t)__bfloat16_as_ushort(l0) | ((uint32_t)__bfloat16_as_ushort(l1) << 16);
        L.y = (uint32_t)__bfloat16_as_ushort(l2) | ((uint32_t)__bfloat16_as_ushort(l3) << 16);
        ph2[k] = H; pl2[k] = L;
    }
}

// ---------------- host ----------------------------------------------------------
extern "C" void kernel_launch(void* const* d_in, const int* in_sizes, int n_in,
                              void* d_out, int out_size)
{
    const float* x    = (const float*)d_in[0];
    const float* qin  = (const float*)d_in[1];
    const float* vin  = (const float*)d_in[2];
    const float* mask = (const float*)d_in[3];
    const float* Wk   = (const float*)d_in[4];
    const float* Wqs  = (const float*)d_in[5];
    const float* Wqo  = (const float*)d_in[6];
    const float* Wv   = (const float*)d_in[7];

    #define SYMP(T, p, s) T* p; { void* _t; cudaGetSymbolAddress(&_t, s); p = (T*)_t; }
    SYMP(__nv_bfloat16, xh,  g_xh)  SYMP(__nv_bfloat16, xl,  g_xl)
    SYMP(__nv_bfloat16, qih, g_qih) SYMP(__nv_bfloat16, qil, g_qil)
    SYMP(__nv_bfloat16, vih, g_vih) SYMP(__nv_bfloat16, vil, g_vil)
    SYMP(__nv_bfloat16, wkh, g_wkh) SYMP(__nv_bfloat16, wkl, g_wkl)
    SYMP(__nv_bfloat16, wqsh,g_wqsh)SYMP(__nv_bfloat16, wqsl,g_wqsl)
    SYMP(__nv_bfloat16, wqoh,g_wqoh)SYMP(__nv_bfloat16, wqol,g_wqol)
    SYMP(__nv_bfloat16, wvh, g_wvh) SYMP(__nv_bfloat16, wvl, g_wvl)
    SYMP(__nv_bfloat16, kh,  g_kh)  SYMP(__nv_bfloat16, kl,  g_kl)
    SYMP(__nv_bfloat16, qsh, g_qsh) SYMP(__nv_bfloat16, qsl, g_qsl)
    SYMP(__nv_bfloat16, qoh, g_qoh) SYMP(__nv_bfloat16, qol, g_qol)
    SYMP(__nv_bfloat16, vth, g_vth) SYMP(__nv_bfloat16, vtl, g_vtl)
    SYMP(__nv_bfloat16, ph,  g_ph)  SYMP(__nv_bfloat16, pl,  g_pl)
    SYMP(float, po, g_po)

    float* out   = (float*)d_out;
    float* pself = out + ND;

    cudaFuncSetAttribute(gemm_proj,   cudaFuncAttributeMaxDynamicSharedMemorySize, GEMM_SMEM);
    cudaFuncSetAttribute(gemm_scores, cudaFuncAttributeMaxDynamicSharedMemorySize, GEMM_SMEM);
    cudaFuncSetAttribute(gemm_pv,     cudaFuncAttributeMaxDynamicSharedMemorySize, GEMM_SMEM);

    // 1) split inputs to bf16 hi/lo (merged, grid-strided)
    const int ND4 = (int)(ND / 4), NW4 = (int)(NW / 4);
    {
        SplitP sp;
        sp.in[0] = (const float4*)x;   sp.hi[0] = (uint2*)xh;  sp.lo[0] = (uint2*)xl;
        sp.in[1] = (const float4*)qin; sp.hi[1] = (uint2*)qih; sp.lo[1] = (uint2*)qil;
        sp.in[2] = (const float4*)vin; sp.hi[2] = (uint2*)vih; sp.lo[2] = (uint2*)vil;
        sp.in[3] = sp.in[0]; sp.hi[3] = sp.hi[0]; sp.lo[3] = sp.lo[0]; // unused
        split_many<<<dim3(1184, 3), 256>>>(sp, ND4);

        SplitP sw;
        sw.in[0] = (const float4*)Wk;  sw.hi[0] = (uint2*)wkh;  sw.lo[0] = (uint2*)wkl;
        sw.in[1] = (const float4*)Wqs; sw.hi[1] = (uint2*)wqsh; sw.lo[1] = (uint2*)wqsl;
        sw.in[2] = (const float4*)Wqo; sw.hi[2] = (uint2*)wqoh; sw.lo[2] = (uint2*)wqol;
        sw.in[3] = (const float4*)Wv;  sw.hi[3] = (uint2*)wvh;  sw.lo[3] = (uint2*)wvl;
        split_many<<<dim3(296, 4), 256>>>(sw, NW4);
    }

    // 2) projections merged into ONE launch (z selects GEMM); z==3 (V) writes V^T
    {
        ProjP pp;
        pp.Ah[0] = xh;  pp.Al[0] = xl;  pp.Bh[0] = wkh;  pp.Bl[0] = wkl;  pp.Ch[0] = kh;  pp.Cl[0] = kl;
        pp.Ah[1] = xh;  pp.Al[1] = xl;  pp.Bh[1] = wqsh; pp.Bl[1] = wqsl; pp.Ch[1] = qsh; pp.Cl[1] = qsl;
        pp.Ah[2] = qih; pp.Al[2] = qil; pp.Bh[2] = wqoh; pp.Bl[2] = wqol; pp.Ch[2] = qoh; pp.Cl[2] = qol;
        pp.Ah[3] = vih; pp.Al[3] = vil; pp.Bh[3] = wvh;  pp.Bl[3] = wvl;  pp.Ch[3] = vth; pp.Cl[3] = vtl;
        gemm_proj<<<dim3(8, 64, 4), 256, GEMM_SMEM>>>(pp);
    }

    // 3) scores merged into ONE launch (z = which*8 + batch), M=N=2048, K=1024
    {
        ScoreP sc;
        sc.Qh[0] = qsh; sc.Ql[0] = qsl; sc.C[0] = pself;
        sc.Qh[1] = qoh; sc.Ql[1] = qol; sc.C[1] = po;
        sc.Kh = kh; sc.Kl = kl;
        gemm_scores<<<dim3(16, 8, 16), 256, GEMM_SMEM>>>(sc);
    }

    // 4) dual softmax; emits p_self fp32 + combined-p bf16 split
    softmax_combine<<<B_ * L_, 256>>>(mask, pself, po, ph, pl);

    // 5) out = (p_self + p_other) @ V  (batched NT vs V^T, M=2048, N=1024, K=2048)
    gemm_pv<<<dim3(8, 8, 8), 256, GEMM_SMEM>>>(ph, pl, vth, vtl, out);
}

// round 16
// speedup vs baseline: 1.0011x; 1.0011x over previous
#include <cuda_runtime.h>
#include <cuda_bf16.h>
#include <math.h>
#include <stdint.h>

#define B_ 8
#define L_ 2048
#define D_ 1024

static const size_t ND = (size_t)B_ * L_ * D_;   // 16,777,216
static const size_t NW = (size_t)D_ * D_;        // 1,048,576

// ---------------- device scratch (globals: no allocation APIs) ----------------
#define GBUF(name, n) __device__ __align__(256) __nv_bfloat16 name[n]
GBUF(g_xh, 16777216);  GBUF(g_xl, 16777216);
GBUF(g_qih, 16777216); GBUF(g_qil, 16777216);
GBUF(g_vih, 16777216); GBUF(g_vil, 16777216);
GBUF(g_wkh, 1048576);  GBUF(g_wkl, 1048576);
GBUF(g_wqsh, 1048576); GBUF(g_wqsl, 1048576);
GBUF(g_wqoh, 1048576); GBUF(g_wqol, 1048576);
GBUF(g_wvh, 1048576);  GBUF(g_wvl, 1048576);
GBUF(g_kh, 16777216);  GBUF(g_kl, 16777216);
GBUF(g_qsh, 16777216); GBUF(g_qsl, 16777216);
GBUF(g_qoh, 16777216); GBUF(g_qol, 16777216);
GBUF(g_vth, 16777216); GBUF(g_vtl, 16777216);   // V^T hi/lo, written by proj epilogue
GBUF(g_ph, 33554432);  GBUF(g_pl, 33554432);
__device__ __align__(256) float g_po[33554432];

// ---------------- PTX helpers (base sm_103 target: NO tcgen05/TMA) ------------
__device__ __forceinline__ uint32_t smem_u32(const void* p) {
    uint32_t a;
    asm("{ .reg .u64 t; cvta.to.shared.u64 t, %1; cvt.u32.u64 %0, t; }" : "=r"(a) : "l"(p));
    return a;
}

#define CPASYNC(saddr, gptr) \
    asm volatile("cp.async.cg.shared.global [%0], [%1], 16;" \
                 :: "r"(saddr), "l"(gptr) : "memory")
#define CP_COMMIT() asm volatile("cp.async.commit_group;" ::: "memory")
#define CP_WAIT2()  asm volatile("cp.async.wait_group 2;" ::: "memory")

__device__ __forceinline__ void ldmx4(uint32_t* r, uint32_t addr) {
    asm volatile("ldmatrix.sync.aligned.m8n8.x4.shared.b16 {%0,%1,%2,%3}, [%4];"
                 : "=r"(r[0]), "=r"(r[1]), "=r"(r[2]), "=r"(r[3]) : "r"(addr));
}

__device__ __forceinline__ void mma16816(float* c, const uint32_t* a, const uint32_t* b) {
    asm volatile(
        "mma.sync.aligned.m16n8k16.row.col.f32.bf16.bf16.f32 "
        "{%0,%1,%2,%3}, {%4,%5,%6,%7}, {%8,%9}, {%0,%1,%2,%3};"
        : "+f"(c[0]), "+f"(c[1]), "+f"(c[2]), "+f"(c[3])
        : "r"(a[0]), "r"(a[1]), "r"(a[2]), "r"(a[3]), "r"(b[0]), "r"(b[1]));
}

// smem tile rows of 32 bf16 (64B, 4x16B chunks), XOR swizzle on chunk.
__device__ __forceinline__ uint32_t swz(int row, int chunk) {
    return (uint32_t)(row * 64 + (((chunk ^ ((row >> 1) & 3)) & 3) << 4));
}

__device__ __forceinline__ void split2(float v, __nv_bfloat16& h, __nv_bfloat16& l) {
    h = __float2bfloat16(v);
    l = __float2bfloat16(v - __bfloat162float(h));
}

// ---------------- pipelined bf16x3 warp-MMA GEMM body (NT) --------------------
// C[m,n] = sum_k (Ah+Al)[m,k]*(Bh+Bl)[n,k]   (Al*Bl dropped)
// CTA 256x128xK, Kstep=32, 4 stages, 8 warps (4m x 2n), warp tile 64x64.
// Stage layout: Ah[256x32]@0 (16KB), Al@16K, Bh[128x32]@32K (8KB), Bl@40K.
// EPI=0: fp32 C.  EPI=1: bf16 hi/lo split (Ch, Cl).
// EPI=2: bf16 hi/lo split stored TRANSPOSED (Ch/Cl are [B, N-dim, M-dim],
//        row stride ldc, batch = m0>>11 of the flattened M) via smem staging.
#define STG_BYTES 49152
#define GEMM_SMEM (4 * STG_BYTES)   // 192 KB

template <int EPI>
__device__ __forceinline__ void
gemm_body(const __nv_bfloat16* __restrict__ Ah, const __nv_bfloat16* __restrict__ Al,
          const __nv_bfloat16* __restrict__ Bh, const __nv_bfloat16* __restrict__ Bl,
          float* __restrict__ C, __nv_bfloat16* __restrict__ Ch, __nv_bfloat16* __restrict__ Cl,
          int K, int ldc, int m0, int n0)
{
    extern __shared__ __align__(128) char smem[];
    const uint32_t smemU = smem_u32(smem);

    const int tid  = threadIdx.x;
    const int wid  = tid >> 5;
    const int lane = tid & 31;

    const int wm64 = (wid & 3) * 64;
    const int wn64 = (wid >> 2) * 64;

    float acc[128];
    #pragma unroll
    for (int i = 0; i < 128; i++) acc[i] = 0.0f;

    const int KT = K >> 5;   // k-steps of 32

    #define ISSUE_STAGE(KF, SLOT) do {                                        \
        uint32_t _sb = smemU + (uint32_t)(SLOT) * STG_BYTES;                  \
        size_t _ko = (size_t)(KF) * 32;                                       \
        _Pragma("unroll")                                                     \
        for (int _i = 0; _i < 4; _i++) {                                      \
            int _c = tid + _i * 256;                                          \
            int _r = _c >> 2, _ch = _c & 3;                                   \
            uint32_t _so = swz(_r, _ch);                                      \
            size_t _go = (size_t)(m0 + _r) * K + _ko + (size_t)_ch * 8;       \
            CPASYNC(_sb + _so,          Ah + _go);                            \
            CPASYNC(_sb + 16384u + _so, Al + _go);                            \
        }                                                                     \
        _Pragma("unroll")                                                     \
        for (int _i = 0; _i < 2; _i++) {                                      \
            int _c = tid + _i * 256;                                          \
            int _r = _c >> 2, _ch = _c & 3;                                   \
            uint32_t _so = swz(_r, _ch);                                      \
            size_t _go = (size_t)(n0 + _r) * K + _ko + (size_t)_ch * 8;       \
            CPASYNC(_sb + 32768u + _so, Bh + _go);                            \
            CPASYNC(_sb + 40960u + _so, Bl + _go);                            \
        }                                                                     \
    } while (0)

    // prologue: fill 3 stages
    ISSUE_STAGE(0, 0); CP_COMMIT();
    ISSUE_STAGE(1, 1); CP_COMMIT();
    ISSUE_STAGE(2, 2); CP_COMMIT();

    for (int kt = 0; kt < KT; kt++) {
        CP_WAIT2();
        __syncthreads();

        int kf = kt + 3;
        if (kf < KT) ISSUE_STAGE(kf, kf & 3);
        CP_COMMIT();

        const uint32_t sb = smemU + (uint32_t)(kt & 3) * STG_BYTES;
        #pragma unroll
        for (int k16 = 0; k16 < 2; k16++) {
            uint32_t bh[16], bl[16];
            #pragma unroll
            for (int tp = 0; tp < 4; tp++) {
                int brow = wn64 + tp * 16 + (lane & 7) + ((lane >> 4) << 3);
                int bch  = k16 * 2 + ((lane >> 3) & 1);
                uint32_t off = swz(brow, bch);
                ldmx4(&bh[tp * 4], sb + 32768u + off);
                ldmx4(&bl[tp * 4], sb + 40960u + off);
            }
            #pragma unroll
            for (int tm = 0; tm < 4; tm++) {
                int arow = wm64 + tm * 16 + (lane & 15);
                int ach  = k16 * 2 + (lane >> 4);
                uint32_t off = swz(arow, ach);
                uint32_t ah[4], al[4];
                ldmx4(ah, sb + off);
                ldmx4(al, sb + 16384u + off);
                #pragma unroll
                for (int tn = 0; tn < 8; tn++) {
                    float* c = acc + (tm * 8 + tn) * 4;
                    mma16816(c, ah, &bh[tn * 2]);
                    mma16816(c, al, &bh[tn * 2]);
                    mma16816(c, ah, &bl[tn * 2]);
                }
            }
        }
    }
    #undef ISSUE_STAGE

    if (EPI == 2) {
        // ---- transposed split epilogue via smem staging ----
        // stage: hi/lo tiles as [128 n][TS m-padded] bf16
        const int TS = 272;   // padded m-stride (banks spread)
        __nv_bfloat16* sh = reinterpret_cast<__nv_bfloat16*>(smem);
        __nv_bfloat16* sl = sh + 128 * TS;

        __syncthreads();   // mainloop smem no longer needed
        #pragma unroll
        for (int tm = 0; tm < 4; tm++) {
            #pragma unroll
            for (int tn = 0; tn < 8; tn++) {
                const float* c = acc + (tm * 8 + tn) * 4;
                int rl = wm64 + tm * 16 + (lane >> 2);      // local m (0..255)
                int cl = wn64 + tn * 8 + (lane & 3) * 2;    // local n (0..127)
                __nv_bfloat16 h, l;
                split2(c[0], h, l); sh[cl * TS + rl] = h;       sl[cl * TS + rl] = l;
                split2(c[1], h, l); sh[(cl + 1) * TS + rl] = h; sl[(cl + 1) * TS + rl] = l;
                split2(c[2], h, l); sh[cl * TS + rl + 8] = h;   sl[cl * TS + rl + 8] = l;
                split2(c[3], h, l); sh[(cl + 1) * TS + rl + 8] = h; sl[(cl + 1) * TS + rl + 8] = l;
            }
        }
        __syncthreads();

        // write out: C^T tile rows = n0..n0+127 (d), cols = m-range (l), per-batch
        const size_t base = (size_t)(m0 >> 11) * ((size_t)D_ * L_) + (m0 & 2047);
        #pragma unroll
        for (int j = 0; j < 64; j++) {
            int idx = tid + j * 256;          // 16384 uint32 per tile
            int nl  = idx >> 7;
            int ml2 = (idx & 127) * 2;
            uint32_t hp = (uint32_t)__bfloat16_as_ushort(sh[nl * TS + ml2]) |
                          ((uint32_t)__bfloat16_as_ushort(sh[nl * TS + ml2 + 1]) << 16);
            uint32_t lp = (uint32_t)__bfloat16_as_ushort(sl[nl * TS + ml2]) |
                          ((uint32_t)__bfloat16_as_ushort(sl[nl * TS + ml2 + 1]) << 16);
            size_t gx = base + (size_t)(n0 + nl) * L_ + ml2;
            *(uint32_t*)(Ch + gx) = hp;
            *(uint32_t*)(Cl + gx) = lp;
        }
        return;
    }

    // epilogue: direct stores from mma accumulator layout
    #pragma unroll
    for (int tm = 0; tm < 4; tm++) {
        #pragma unroll
        for (int tn = 0; tn < 8; tn++) {
            const float* c = acc + (tm * 8 + tn) * 4;
            int row0 = m0 + wm64 + tm * 16 + (lane >> 2);
            int col  = n0 + wn64 + tn * 8 + (lane & 3) * 2;
            size_t i0 = (size_t)row0 * ldc + col;
            size_t i1 = i0 + (size_t)8 * ldc;
            if (EPI == 0) {
                *(float2*)(C + i0) = make_float2(c[0], c[1]);
                *(float2*)(C + i1) = make_float2(c[2], c[3]);
            } else {
                #pragma unroll
                for (int p = 0; p < 2; p++) {
                    size_t ix = p ? i1 : i0;
                    __nv_bfloat16 h0, l0, h1, l1;
                    split2(c[p * 2], h0, l0);
                    split2(c[p * 2 + 1], h1, l1);
                    uint32_t hp = (uint32_t)__bfloat16_as_ushort(h0) |
                                  ((uint32_t)__bfloat16_as_ushort(h1) << 16);
                    uint32_t lp = (uint32_t)__bfloat16_as_ushort(l0) |
                                  ((uint32_t)__bfloat16_as_ushort(l1) << 16);
                    *(uint32_t*)(Ch + ix) = hp;
                    *(uint32_t*)(Cl + ix) = lp;
                }
            }
        }
    }
}

// ---- merged projection GEMM: z selects one of 4 (A, W, C) tuples --------------
// z==3 is the V projection: writes V^T hi/lo directly (EPI=2).
struct ProjP {
    const __nv_bfloat16 *Ah[4], *Al[4], *Bh[4], *Bl[4];
    __nv_bfloat16 *Ch[4], *Cl[4];
};
__global__ void __launch_bounds__(256, 1)
gemm_proj(ProjP p)
{
    const int g  = blockIdx.z;
    const int m0 = blockIdx.y * 256, n0 = blockIdx.x * 128;
    if (g == 3)
        gemm_body<2>(p.Ah[3], p.Al[3], p.Bh[3], p.Bl[3],
                     nullptr, p.Ch[3], p.Cl[3], 1024, 2048, m0, n0);
    else
        gemm_body<1>(p.Ah[g], p.Al[g], p.Bh[g], p.Bl[g],
                     nullptr, p.Ch[g], p.Cl[g], 1024, 1024, m0, n0);
}

// ---- merged score GEMMs: z = which*8 + batch -----------------------------------
struct ScoreP {
    const __nv_bfloat16 *Qh[2], *Ql[2];
    const __nv_bfloat16 *Kh, *Kl;
    float *C[2];
};
__global__ void __launch_bounds__(256, 1)
gemm_scores(ScoreP p)
{
    const int z = blockIdx.z;
    const int b = z & 7, w = z >> 3;
    const size_t offA = (size_t)b * L_ * D_;
    const int m0 = blockIdx.y * 256, n0 = blockIdx.x * 128;
    gemm_body<0>(p.Qh[w] + offA, p.Ql[w] + offA, p.Kh + offA, p.Kl + offA,
                 p.C[w] + (size_t)b * L_ * L_, nullptr, nullptr, 1024, 2048, m0, n0);
}

// ---- PV GEMM: z = batch ---------------------------------------------------------
__global__ void __launch_bounds__(256, 1)
gemm_pv(const __nv_bfloat16* __restrict__ Ah, const __nv_bfloat16* __restrict__ Al,
        const __nv_bfloat16* __restrict__ Bh, const __nv_bfloat16* __restrict__ Bl,
        float* __restrict__ C)
{
    const size_t z = blockIdx.z;
    const int m0 = blockIdx.y * 256, n0 = blockIdx.x * 128;
    gemm_body<0>(Ah + z * ((size_t)L_ * L_), Al + z * ((size_t)L_ * L_),
                 Bh + z * ((size_t)D_ * L_), Bl + z * ((size_t)D_ * L_),
                 C + z * ((size_t)L_ * D_), nullptr, nullptr, 2048, 1024, m0, n0);
}

// ---------------- fp32 -> bf16 hi/lo split, merged + grid-strided ---------------
struct SplitP { const float4* in[4]; uint2* hi[4]; uint2* lo[4]; };

__global__ void __launch_bounds__(256)
split_many(SplitP p, int n4)
{
    const int g = blockIdx.y;
    const float4* in = p.in[g];
    uint2* hi = p.hi[g];
    uint2* lo = p.lo[g];
    const int stride = gridDim.x * 256;
    for (int i = blockIdx.x * 256 + threadIdx.x; i < n4; i += stride) {
        float4 v = in[i];
        __nv_bfloat16 h0, l0, h1, l1, h2, l2, h3, l3;
        split2(v.x, h0, l0); split2(v.y, h1, l1);
        split2(v.z, h2, l2); split2(v.w, h3, l3);
        uint2 H, L;
        H.x = (uint32_t)__bfloat16_as_ushort(h0) | ((uint32_t)__bfloat16_as_ushort(h1) << 16);
        H.y = (uint32_t)__bfloat16_as_ushort(h2) | ((uint32_t)__bfloat16_as_ushort(h3) << 16);
        L.x = (uint32_t)__bfloat16_as_ushort(l0) | ((uint32_t)__bfloat16_as_ushort(l1) << 16);
        L.y = (uint32_t)__bfloat16_as_ushort(l2) | ((uint32_t)__bfloat16_as_ushort(l3) << 16);
        hi[i] = H; lo[i] = L;
    }
}

// ---------------- dual softmax + combined-p bf16 split (float4 vectorized) ------
__global__ void __launch_bounds__(256)
softmax_combine(const float* __restrict__ mask,
                float* __restrict__ psf,          // raw self scores -> p_self (fp32 out)
                const float* __restrict__ po,     // raw other scores
                __nv_bfloat16* __restrict__ ph,   // (p_self+p_other) hi
                __nv_bfloat16* __restrict__ pl)   // (p_self+p_other) lo
{
    const int row = blockIdx.x;
    const int b   = row >> 11;
    float4* ps4 = (float4*)(psf + (size_t)row * L_);
    const float4* pc4 = (const float4*)(po + (size_t)row * L_);
    uint2* ph2 = (uint2*)(ph + (size_t)row * L_);
    uint2* pl2 = (uint2*)(pl + (size_t)row * L_);
    const float4* mk4 = (const float4*)(mask + (size_t)b * L_);

    const int t = threadIdx.x;
    const float scale = 0.03125f;

    float s[8], o[8];
    #pragma unroll
    for (int j = 0; j < 2; j++) {
        int k = t + j * 256;            // float4 index, 512 per row
        float4 sv = ps4[k];
        float4 ov = pc4[k];
        float4 mv = mk4[k];
        float p0 = (1.0f - mv.x) * -100000.0f;
        float p1 = (1.0f - mv.y) * -100000.0f;
        float p2 = (1.0f - mv.z) * -100000.0f;
        float p3 = (1.0f - mv.w) * -100000.0f;
        s[j*4+0] = sv.x * scale + p0;  o[j*4+0] = ov.x * scale + p0;
        s[j*4+1] = sv.y * scale + p1;  o[j*4+1] = ov.y * scale + p1;
        s[j*4+2] = sv.z * scale + p2;  o[j*4+2] = ov.z * scale + p2;
        s[j*4+3] = sv.w * scale + p3;  o[j*4+3] = ov.w * scale + p3;
    }

    __shared__ float red[2][8];
    const int w = t >> 5, ln = t & 31;

    float ms = -INFINITY, mo = -INFINITY;
    #pragma unroll
    for (int j = 0; j < 8; j++) { ms = fmaxf(ms, s[j]); mo = fmaxf(mo, o[j]); }
    #pragma unroll
    for (int off = 16; off; off >>= 1) {
        ms = fmaxf(ms, __shfl_xor_sync(0xffffffffu, ms, off));
        mo = fmaxf(mo, __shfl_xor_sync(0xffffffffu, mo, off));
    }
    if (ln == 0) { red[0][w] = ms; red[1][w] = mo; }
    __syncthreads();
    ms = red[0][0]; mo = red[1][0];
    #pragma unroll
    for (int i = 1; i < 8; i++) { ms = fmaxf(ms, red[0][i]); mo = fmaxf(mo, red[1][i]); }
    __syncthreads();

    float ss = 0.0f, so = 0.0f;
    #pragma unroll
    for (int j = 0; j < 8; j++) {
        s[j] = expf(s[j] - ms); ss += s[j];
        o[j] = expf(o[j] - mo); so += o[j];
    }
    #pragma unroll
    for (int off = 16; off; off >>= 1) {
        ss += __shfl_xor_sync(0xffffffffu, ss, off);
        so += __shfl_xor_sync(0xffffffffu, so, off);
    }
    if (ln == 0) { red[0][w] = ss; red[1][w] = so; }
    __syncthreads();
    ss = 0.0f; so = 0.0f;
    #pragma unroll
    for (int i = 0; i < 8; i++) { ss += red[0][i]; so += red[1][i]; }

    const float rs = 1.0f / ss, ro = 1.0f / so;
    #pragma unroll
    for (int j = 0; j < 2; j++) {
        int k = t + j * 256;
        float a0 = s[j*4+0] * rs, a1 = s[j*4+1] * rs;
        float a2 = s[j*4+2] * rs, a3 = s[j*4+3] * rs;
        ps4[k] = make_float4(a0, a1, a2, a3);
        float c0 = a0 + o[j*4+0] * ro, c1 = a1 + o[j*4+1] * ro;
        float c2 = a2 + o[j*4+2] * ro, c3 = a3 + o[j*4+3] * ro;
        __nv_bfloat16 h0, l0, h1, l1, h2, l2, h3, l3;
        split2(c0, h0, l0); split2(c1, h1, l1);
        split2(c2, h2, l2); split2(c3, h3, l3);
        uint2 H, L;
        H.x = (uint32_t)__bfloat16_as_ushort(h0) | ((uint32_t)__bfloat16_as_ushort(h1) << 16);
        H.y = (uint32_t)__bfloat16_as_ushort(h2) | ((uint32_t)__bfloat16_as_ushort(h3) << 16);
        L.x = (uint32_t)__bfloat16_as_ushort(l0) | ((uint32_t)__bfloat16_as_ushort(l1) << 16);
        L.y = (uint32_t)__bfloat16_as_ushort(l2) | ((uint32_t)__bfloat16_as_ushort(l3) << 16);
        ph2[k] = H; pl2[k] = L;
    }
}

// ---------------- host ----------------------------------------------------------
extern "C" void kernel_launch(void* const* d_in, const int* in_sizes, int n_in,
                              void* d_out, int out_size)
{
    const float* x    = (const float*)d_in[0];
    const float* qin  = (const float*)d_in[1];
    const float* vin  = (const float*)d_in[2];
    const float* mask = (const float*)d_in[3];
    const float* Wk   = (const float*)d_in[4];
    const float* Wqs  = (const float*)d_in[5];
    const float* Wqo  = (const float*)d_in[6];
    const float* Wv   = (const float*)d_in[7];

    #define SYMP(T, p, s) T* p; { void* _t; cudaGetSymbolAddress(&_t, s); p = (T*)_t; }
    SYMP(__nv_bfloat16, xh,  g_xh)  SYMP(__nv_bfloat16, xl,  g_xl)
    SYMP(__nv_bfloat16, qih, g_qih) SYMP(__nv_bfloat16, qil, g_qil)
    SYMP(__nv_bfloat16, vih, g_vih) SYMP(__nv_bfloat16, vil, g_vil)
    SYMP(__nv_bfloat16, wkh, g_wkh) SYMP(__nv_bfloat16, wkl, g_wkl)
    SYMP(__nv_bfloat16, wqsh,g_wqsh)SYMP(__nv_bfloat16, wqsl,g_wqsl)
    SYMP(__nv_bfloat16, wqoh,g_wqoh)SYMP(__nv_bfloat16, wqol,g_wqol)
    SYMP(__nv_bfloat16, wvh, g_wvh) SYMP(__nv_bfloat16, wvl, g_wvl)
    SYMP(__nv_bfloat16, kh,  g_kh)  SYMP(__nv_bfloat16, kl,  g_kl)
    SYMP(__nv_bfloat16, qsh, g_qsh) SYMP(__nv_bfloat16, qsl, g_qsl)
    SYMP(__nv_bfloat16, qoh, g_qoh) SYMP(__nv_bfloat16, qol, g_qol)
    SYMP(__nv_bfloat16, vth, g_vth) SYMP(__nv_bfloat16, vtl, g_vtl)
    SYMP(__nv_bfloat16, ph,  g_ph)  SYMP(__nv_bfloat16, pl,  g_pl)
    SYMP(float, po, g_po)

    float* out   = (float*)d_out;
    float* pself = out + ND;

    cudaFuncSetAttribute(gemm_proj,   cudaFuncAttributeMaxDynamicSharedMemorySize, GEMM_SMEM);
    cudaFuncSetAttribute(gemm_scores, cudaFuncAttributeMaxDynamicSharedMemorySize, GEMM_SMEM);
    cudaFuncSetAttribute(gemm_pv,     cudaFuncAttributeMaxDynamicSharedMemorySize, GEMM_SMEM);

    // 1) split inputs to bf16 hi/lo (merged, grid-strided)
    const int ND4 = (int)(ND / 4), NW4 = (int)(NW / 4);
    {
        SplitP sp;
        sp.in[0] = (const float4*)x;   sp.hi[0] = (uint2*)xh;  sp.lo[0] = (uint2*)xl;
        sp.in[1] = (const float4*)qin; sp.hi[1] = (uint2*)qih; sp.lo[1] = (uint2*)qil;
        sp.in[2] = (const float4*)vin; sp.hi[2] = (uint2*)vih; sp.lo[2] = (uint2*)vil;
        sp.in[3] = sp.in[0]; sp.hi[3] = sp.hi[0]; sp.lo[3] = sp.lo[0]; // unused
        split_many<<<dim3(1184, 3), 256>>>(sp, ND4);

        SplitP sw;
        sw.in[0] = (const float4*)Wk;  sw.hi[0] = (uint2*)wkh;  sw.lo[0] = (uint2*)wkl;
        sw.in[1] = (const float4*)Wqs; sw.hi[1] = (uint2*)wqsh; sw.lo[1] = (uint2*)wqsl;
        sw.in[2] = (const float4*)Wqo; sw.hi[2] = (uint2*)wqoh; sw.lo[2] = (uint2*)wqol;
        sw.in[3] = (const float4*)Wv;  sw.hi[3] = (uint2*)wvh;  sw.lo[3] = (uint2*)wvl;
        split_many<<<dim3(296, 4), 256>>>(sw, NW4);
    }

    // 2) projections merged into ONE launch (z selects GEMM); z==3 (V) writes V^T
    {
        ProjP pp;
        pp.Ah[0] = xh;  pp.Al[0] = xl;  pp.Bh[0] = wkh;  pp.Bl[0] = wkl;  pp.Ch[0] = kh;  pp.Cl[0] = kl;
        pp.Ah[1] = xh;  pp.Al[1] = xl;  pp.Bh[1] = wqsh; pp.Bl[1] = wqsl; pp.Ch[1] = qsh; pp.Cl[1] = qsl;
        pp.Ah[2] = qih; pp.Al[2] = qil; pp.Bh[2] = wqoh; pp.Bl[2] = wqol; pp.Ch[2] = qoh; pp.Cl[2] = qol;
        pp.Ah[3] = vih; pp.Al[3] = vil; pp.Bh[3] = wvh;  pp.Bl[3] = wvl;  pp.Ch[3] = vth; pp.Cl[3] = vtl;
        gemm_proj<<<dim3(8, 64, 4), 256, GEMM_SMEM>>>(pp);
    }

    // 3) scores merged into ONE launch (z = which*8 + batch), M=N=2048, K=1024
    {
        ScoreP sc;
        sc.Qh[0] = qsh; sc.Ql[0] = qsl; sc.C[0] = pself;
        sc.Qh[1] = qoh; sc.Ql[1] = qol; sc.C[1] = po;
        sc.Kh = kh; sc.Kl = kl;
        gemm_scores<<<dim3(16, 8, 16), 256, GEMM_SMEM>>>(sc);
    }

    // 4) dual softmax; emits p_self fp32 + combined-p bf16 split
    softmax_combine<<<B_ * L_, 256>>>(mask, pself, po, ph, pl);

    // 5) out = (p_self + p_other) @ V  (batched NT vs V^T, M=2048, N=1024, K=2048)
    gemm_pv<<<dim3(8, 8, 8), 256, GEMM_SMEM>>>(ph, pl, vth, vtl, out);
}